// round 15
// baseline (speedup 1.0000x reference)
#include <cuda_runtime.h>
#include <cuda_fp16.h>
#include <cstdint>

#define Np   262144
#define Bn   4
#define Hn   512
#define Wn   512
#define NINS 16
#define EPSF 1e-5f

// ---------------- device scratch ----------------
__device__ int      g_idx_map[Bn * Hn * Wn];               // after emit: spatial RANK
__device__ int      g_order[Np];                           // rank -> orig index
__device__ int      g_seg_s[Np];                           // seg in rank order
__device__ int      g_blk[1024];                           // compaction counts/offsets
__device__ __align__(16) uint32_t g_hraw[3u * Np * 32u];   // raw h fp16 (rank order)
__device__ __align__(16) uint2    g_hn[3u * Np * 16u];     // relu(norm(h)) fp16 (rank order)
__device__ __align__(16) uint2    g_ftH[Np * 16u];         // feats fp16 (rank order)
__device__ float g_sum [3 * NINS * 64];
__device__ float g_sum2[3 * NINS * 64];
__device__ float g_mean[3 * NINS * 64];
__device__ float g_rinv[3 * NINS * 64];
__device__ int   g_cnt [NINS];
__device__ int   g_ymin[NINS], g_ymax[NINS], g_xmin[NINS], g_xmax[NINS];
__device__ int   g_dil[3 * NINS];
__device__ uint2 g_wtbH[3 * 9 * 1024];
__device__ uint2 g_wtfH[36 * 1024];

// ---------------- helpers ----------------
__device__ __forceinline__ void mma_f16(float* d, uint32_t a0, uint32_t a1,
                                        uint32_t a2, uint32_t a3,
                                        uint32_t b0, uint32_t b1) {
    asm volatile(
        "mma.sync.aligned.m16n8k16.row.col.f32.f16.f16.f32 "
        "{%0,%1,%2,%3}, {%4,%5,%6,%7}, {%8,%9}, {%0,%1,%2,%3};"
        : "+f"(d[0]), "+f"(d[1]), "+f"(d[2]), "+f"(d[3])
        : "r"(a0), "r"(a1), "r"(a2), "r"(a3), "r"(b0), "r"(b1));
}

__device__ __forceinline__ void ldsm_x4(uint32_t* r, uint32_t addr) {
    asm volatile("ldmatrix.sync.aligned.m8n8.x4.shared.b16 {%0,%1,%2,%3}, [%4];"
                 : "=r"(r[0]), "=r"(r[1]), "=r"(r[2]), "=r"(r[3]) : "r"(addr));
}

__device__ __forceinline__ uint32_t pack2(float x, float y) {
    __half2 h = __floats2half2_rn(x, y);
    return *(uint32_t*)&h;
}

__device__ __forceinline__ void cp_async16(uint32_t dst, const void* src, int srcsize) {
    asm volatile("cp.async.ca.shared.global [%0], [%1], 16, %2;"
                 :: "r"(dst), "l"(src), "r"(srcsize) : "memory");
}
#define CP_COMMIT() asm volatile("cp.async.commit_group;" ::: "memory")
#define CP_WAIT1()  asm volatile("cp.async.wait_group 1;" ::: "memory")
#define CP_WAIT0()  asm volatile("cp.async.wait_group 0;" ::: "memory")

#define ROWS  256
#define SA_BYTES (ROWS * 144)

// ---------------- init / scatter / dil (proven) ----------------
__global__ void k_init() {
    int i = blockIdx.x * blockDim.x + threadIdx.x;
    if (i < Bn * Hn * Wn) g_idx_map[i] = -1;
    if (i < 3 * NINS * 64) { g_sum[i] = 0.f; g_sum2[i] = 0.f; }
    if (i < NINS) {
        g_cnt[i] = 0;
        g_ymin[i] = 0x7FFFFFFF; g_ymax[i] = 0x80000000;
        g_xmin[i] = 0x7FFFFFFF; g_xmax[i] = 0x80000000;
    }
}

__global__ void k_scatter(const int* __restrict__ idxs, const int* __restrict__ seg) {
    __shared__ int sy0[NINS], sy1[NINS], sx0[NINS], sx1[NINS], sc[NINS];
    int tid = threadIdx.x;
    if (tid < NINS) { sy0[tid] = 0x7FFFFFFF; sy1[tid] = 0x80000000;
                      sx0[tid] = 0x7FFFFFFF; sx1[tid] = 0x80000000; sc[tid] = 0; }
    __syncthreads();
    int i = blockIdx.x * blockDim.x + tid;
    if (i < Np) {
        int b = idxs[3*i], y = idxs[3*i+1], x = idxs[3*i+2];
        g_idx_map[(b * Hn + y) * Wn + x] = i;
        int s = seg[i];
        atomicMin(&sy0[s], y); atomicMax(&sy1[s], y);
        atomicMin(&sx0[s], x); atomicMax(&sx1[s], x);
        atomicAdd(&sc[s], 1);
    }
    __syncthreads();
    if (tid < NINS && sc[tid] > 0) {
        atomicMin(&g_ymin[tid], sy0[tid]); atomicMax(&g_ymax[tid], sy1[tid]);
        atomicMin(&g_xmin[tid], sx0[tid]); atomicMax(&g_xmax[tid], sx1[tid]);
        atomicAdd(&g_cnt[tid], sc[tid]);
    }
}

__global__ void k_dil() {
    int i = threadIdx.x;
    if (i < 3 * NINS) {
        int s = i & 15, r = i >> 4;
        int rate = (r == 0) ? 1 : (r == 1) ? 3 : 5;
        float hr = (float)(g_ymax[s] - g_ymin[s]) / (float)Hn;
        float wr = (float)(g_xmax[s] - g_xmin[s]) / (float)Wn;
        int d = (int)ceilf(fmaxf(hr, wr) * (float)rate);
        if (d < 1) d = 1;
        g_dil[r * NINS + s] = d;
    }
}

// ---------------- spatial compaction: count / scan / emit -------------------
__global__ void __launch_bounds__(1024) k_count() {
    int cell = blockIdx.x * 1024 + threadIdx.x;
    int c = __syncthreads_count(g_idx_map[cell] >= 0);
    if (threadIdx.x == 0) g_blk[blockIdx.x] = c;
}

__global__ void __launch_bounds__(1024) k_scan() {
    __shared__ int tmp[1024];
    int t = threadIdx.x;
    int v = g_blk[t];
    tmp[t] = v;
    __syncthreads();
    for (int off = 1; off < 1024; off <<= 1) {
        int add = (t >= off) ? tmp[t - off] : 0;
        __syncthreads();
        tmp[t] += add;
        __syncthreads();
    }
    g_blk[t] = tmp[t] - v;     // exclusive prefix
}

__global__ void __launch_bounds__(1024) k_emit(const int* __restrict__ seg) {
    __shared__ int wbase[32];
    int tid = threadIdx.x;
    int cell = blockIdx.x * 1024 + tid;
    int orig = g_idx_map[cell];
    unsigned mask = __ballot_sync(0xFFFFFFFF, orig >= 0);
    int wid = tid >> 5, lane = tid & 31;
    if (lane == 0) wbase[wid] = __popc(mask);
    __syncthreads();
    if (tid < 32) {
        int own = wbase[tid];
        int v = own;
        for (int o = 1; o < 32; o <<= 1) {
            int n = __shfl_up_sync(0xFFFFFFFF, v, o);
            if (tid >= o) v += n;
        }
        wbase[tid] = v - own;
    }
    __syncthreads();
    if (orig >= 0) {
        int rank = g_blk[blockIdx.x] + wbase[wid] + __popc(mask & ((1u << lane) - 1));
        g_order[rank] = orig;
        g_seg_s[rank] = seg[orig];
        g_idx_map[cell] = rank;
    }
}

// ---------------- weight prep (proven) ----------------
__global__ void k_prepw(const float* __restrict__ w1, const float* __restrict__ w2,
                        const float* __restrict__ w3, const float* __restrict__ wf)
{
    int i = blockIdx.x * blockDim.x + threadIdx.x;
    if (i < 27648) {
        int br  = i / 9216;
        int r   = i % 9216;
        int tap = r / 1024;
        int r2  = r % 1024;
        int s   = r2 >> 8;
        int col = (r2 >> 2) & 63;
        int tig = r2 & 3;
        int kb  = s * 16 + tig * 2;
        const float* w = (br == 0) ? w1 : (br == 1) ? w2 : w3;
        const float* wt = w + tap * 4096;
        g_wtbH[i] = make_uint2(
            pack2(wt[(kb    ) * 64 + col], wt[(kb + 1) * 64 + col]),
            pack2(wt[(kb + 8) * 64 + col], wt[(kb + 9) * 64 + col]));
    } else if (i < 27648 + 36864) {
        int i2  = i - 27648;
        int u   = i2 / 1024;
        int r2  = i2 % 1024;
        int s   = r2 >> 8;
        int col = (r2 >> 2) & 63;
        int tig = r2 & 3;
        int tap = u >> 2, c = u & 3;
        int kb  = c * 64 + s * 16 + tig * 2;
        const float* wt = wf + (size_t)tap * 256 * 64;
        g_wtfH[i2] = make_uint2(
            pack2(wt[(kb    ) * 64 + col], wt[(kb + 1) * 64 + col]),
            pack2(wt[(kb + 8) * 64 + col], wt[(kb + 9) * 64 + col]));
    }
}

// ---------------- feats -> fp16, rank order ----------------
__global__ void __launch_bounds__(256) k_prepf(const float* __restrict__ feats) {
    int i = blockIdx.x * 256 + threadIdx.x;      // Np*16 units
    int rank = i >> 4, li = i & 15;
    int orig = g_order[rank];
    float4 f = ((const float4*)feats)[(size_t)orig * 16 + li];
    g_ftH[i] = make_uint2(pack2(f.x, f.y), pack2(f.z, f.w));
}

// ---------------- branch conv (rank order, no stats) ------------------------
__global__ void __launch_bounds__(256, 2) k_branch_mma(
    const int* __restrict__ idxs,
    const float* __restrict__ bias1, const float* __restrict__ bias2,
    const float* __restrict__ bias3)
{
    extern __shared__ __half smh[];
    char* sA   = (char*)smh;
    int*  snbr = (int*)(sA + 2 * SA_BYTES);

    int tid = threadIdx.x;
    int br  = blockIdx.y;
    int p0  = blockIdx.x * ROWS;
    const float* bias = (br == 0) ? bias1 : (br == 1) ? bias2 : bias3;

    for (int t = tid; t < ROWS * 9; t += 256) {
        int p = t / 9, k = t % 9;
        int gi = p0 + p;
        int orig = g_order[gi];
        int b = idxs[3*orig], y = idxs[3*orig+1], x = idxs[3*orig+2];
        int sgi = g_seg_s[gi];
        int d = g_dil[br * NINS + sgi];
        int ky = k / 3 - 1, kx = k % 3 - 1;
        int ny = y + ky * d, nx = x + kx * d;
        int nbr = -1;
        if (ny >= 0 && ny < Hn && nx >= 0 && nx < Wn) {
            int n = g_idx_map[(b * Hn + ny) * Wn + nx];
            if (n >= 0 && g_seg_s[n] == sgi) nbr = n;
        }
        snbr[t] = nbr;
    }
    __syncthreads();

    int lane = tid & 31, wid = tid >> 5;
    int gid = lane >> 2, tig = lane & 3;
    int li8 = lane & 7, r4 = lane >> 3;
    int lrow = lane & 15, lkh = lane >> 4;

    uint32_t sA_u = (uint32_t)__cvta_generic_to_shared(sA);

    float acc[2][8][4];
#pragma unroll
    for (int mi = 0; mi < 2; mi++)
#pragma unroll
        for (int ni = 0; ni < 8; ni++)
#pragma unroll
            for (int e = 0; e < 4; e++) acc[mi][ni][e] = 0.f;

    const uint2* wtb = g_wtbH + (size_t)(br * 9) * 1024;

    {
#pragma unroll
        for (int j = 0; j < 8; j++) {
            int row = wid * 32 + j * 4 + r4;
            int nbr = snbr[row * 9];
            cp_async16(sA_u + row * 144 + li8 * 16,
                       (const char*)(g_ftH + (size_t)(nbr < 0 ? 0 : nbr) * 16) + li8 * 16,
                       nbr >= 0 ? 16 : 0);
        }
        CP_COMMIT();
    }

    for (int k = 0; k < 9; k++) {
        if (k < 8) {
            uint32_t base = sA_u + ((k + 1) & 1) * SA_BYTES;
#pragma unroll
            for (int j = 0; j < 8; j++) {
                int row = wid * 32 + j * 4 + r4;
                int nbr = snbr[row * 9 + k + 1];
                cp_async16(base + row * 144 + li8 * 16,
                           (const char*)(g_ftH + (size_t)(nbr < 0 ? 0 : nbr) * 16) + li8 * 16,
                           nbr >= 0 ? 16 : 0);
            }
            CP_COMMIT();
            CP_WAIT1();
        } else {
            CP_WAIT0();
        }
        __syncwarp();

        uint32_t sAb_u = sA_u + (k & 1) * SA_BYTES;
        const uint2* wk = wtb + k * 1024;
#pragma unroll
        for (int s = 0; s < 4; s++) {
            uint32_t a[2][4];
#pragma unroll
            for (int mi = 0; mi < 2; mi++) {
                uint32_t addr = sAb_u + (wid * 32 + mi * 16 + lrow) * 144 + s * 32 + lkh * 16;
                ldsm_x4(a[mi], addr);
            }
#pragma unroll
            for (int ni = 0; ni < 8; ni++) {
                uint2 bb = __ldg(wk + (s * 64 + ni * 8 + gid) * 4 + tig);
                mma_f16(acc[0][ni], a[0][0], a[0][1], a[0][2], a[0][3], bb.x, bb.y);
                mma_f16(acc[1][ni], a[1][0], a[1][1], a[1][2], a[1][3], bb.x, bb.y);
            }
        }
        __syncwarp();
    }

    // add bias, write raw h fp16 (rank order)
    uint32_t* hout = g_hraw + (size_t)br * Np * 32;
#pragma unroll
    for (int ni = 0; ni < 8; ni++) {
        int col = ni * 8 + tig * 2;
        float2 bb = *(const float2*)(bias + col);
#pragma unroll
        for (int mi = 0; mi < 2; mi++) {
            int row = p0 + wid * 32 + mi * 16 + gid;
            hout[(size_t)row * 32 + (col >> 1)] =
                pack2(acc[mi][ni][0] + bb.x, acc[mi][ni][1] + bb.y);
            hout[(size_t)(row + 8) * 32 + (col >> 1)] =
                pack2(acc[mi][ni][2] + bb.x, acc[mi][ni][3] + bb.y);
        }
    }
}

// ---------------- stats over g_hraw with smem bins ---------------------------
__global__ void __launch_bounds__(256) k_stats2() {
    __shared__ float sb_sum[NINS * 64], sb_sq[NINS * 64];
    int tid = threadIdx.x;
    int br  = blockIdx.y;
    int base = blockIdx.x * 256;
    for (int i = tid; i < NINS * 64; i += 256) { sb_sum[i] = 0.f; sb_sq[i] = 0.f; }
    __syncthreads();

    int c32 = tid & 31, rg = tid >> 5;           // c32: half2 index, rg: row group
    const uint32_t* hb = g_hraw + (size_t)br * Np * 32;
    for (int r = 0; r < 32; r++) {
        int row = base + rg * 32 + r;
        int sg  = g_seg_s[row];
        uint32_t raw = hb[(size_t)row * 32 + c32];
        float2 f = __half22float2(*reinterpret_cast<const __half2*>(&raw));
        int bidx = sg * 64 + c32 * 2;
        atomicAdd(&sb_sum[bidx],     f.x);
        atomicAdd(&sb_sum[bidx + 1], f.y);
        atomicAdd(&sb_sq [bidx],     f.x * f.x);
        atomicAdd(&sb_sq [bidx + 1], f.y * f.y);
    }
    __syncthreads();
    for (int i = tid; i < NINS * 64; i += 256) {
        if (sb_sum[i] != 0.f || sb_sq[i] != 0.f) {
            atomicAdd(&g_sum [br * NINS * 64 + i], sb_sum[i]);
            atomicAdd(&g_sum2[br * NINS * 64 + i], sb_sq[i]);
        }
    }
}

__global__ void k_normfin() {
    int i = blockIdx.x * blockDim.x + threadIdx.x;
    if (i < 3 * NINS * 64) {
        int sgl = (i / 64) % NINS;
        float cnt = (float)g_cnt[sgl];
        float mean = g_sum[i] / cnt;
        float var  = g_sum2[i] / cnt - mean * mean;
        g_mean[i] = mean;
        g_rinv[i] = rsqrtf(var + EPSF);
    }
}

// ---------------- normalize + relu (rank order) ----------------
__global__ void __launch_bounds__(256) k_hnorm() {
    int i = blockIdx.x * 256 + threadIdx.x;
    int br  = i / (Np * 16);
    int rem = i % (Np * 16);
    int p   = rem >> 4;
    int c4  = rem & 15;
    int sg  = g_seg_s[p];
    uint2 raw = ((const uint2*)g_hraw)[i];
    float2 f01 = __half22float2(*reinterpret_cast<const __half2*>(&raw.x));
    float2 f23 = __half22float2(*reinterpret_cast<const __half2*>(&raw.y));
    int tb = ((br * NINS + sg) << 6) + c4 * 4;
    float4 mm = *(const float4*)(g_mean + tb);
    float4 rr = *(const float4*)(g_rinv + tb);
    float x0 = fmaxf(0.f, (f01.x - mm.x) * rr.x);
    float x1 = fmaxf(0.f, (f01.y - mm.y) * rr.y);
    float x2 = fmaxf(0.f, (f23.x - mm.z) * rr.z);
    float x3 = fmaxf(0.f, (f23.y - mm.w) * rr.w);
    g_hn[i] = make_uint2(pack2(x0, x1), pack2(x2, x3));
}

// ---------------- final conv (rank order, scattered output) ------------------
__global__ void __launch_bounds__(256, 2) k_final_mma(
    const int* __restrict__ idxs, const float* __restrict__ bf,
    float* __restrict__ out)
{
    extern __shared__ __half smh[];
    char* sA   = (char*)smh;
    int*  snbr = (int*)(sA + 2 * SA_BYTES);

    int tid = threadIdx.x;
    int p0  = blockIdx.x * ROWS;

    for (int t = tid; t < ROWS * 9; t += 256) {
        int p = t / 9, k = t % 9;
        int gi = p0 + p;
        int orig = g_order[gi];
        int b = idxs[3*orig], y = idxs[3*orig+1], x = idxs[3*orig+2];
        int ky = k / 3 - 1, kx = k % 3 - 1;
        int ny = y + ky, nx = x + kx;
        int nbr = -1;
        if (ny >= 0 && ny < Hn && nx >= 0 && nx < Wn)
            nbr = g_idx_map[(b * Hn + ny) * Wn + nx];
        snbr[t] = nbr;
    }
    __syncthreads();

    int lane = tid & 31, wid = tid >> 5;
    int gid = lane >> 2, tig = lane & 3;
    int li8 = lane & 7, r4 = lane >> 3;
    int lrow = lane & 15, lkh = lane >> 4;

    uint32_t sA_u = (uint32_t)__cvta_generic_to_shared(sA);

    float acc[2][8][4];
#pragma unroll
    for (int mi = 0; mi < 2; mi++)
#pragma unroll
        for (int ni = 0; ni < 8; ni++)
#pragma unroll
            for (int e = 0; e < 4; e++) acc[mi][ni][e] = 0.f;

    {
#pragma unroll
        for (int j = 0; j < 8; j++) {
            int row = wid * 32 + j * 4 + r4;
            int nbr = snbr[row * 9];
            cp_async16(sA_u + row * 144 + li8 * 16,
                       (const char*)(g_ftH + (size_t)(nbr < 0 ? 0 : nbr) * 16) + li8 * 16,
                       nbr >= 0 ? 16 : 0);
        }
        CP_COMMIT();
    }

    for (int u = 0; u < 36; u++) {
        if (u < 35) {
            int k2 = (u + 1) >> 2, c2 = (u + 1) & 3;
            const uint2* src2 = (c2 == 0) ? g_ftH : (g_hn + (size_t)(c2 - 1) * Np * 16);
            uint32_t base = sA_u + ((u + 1) & 1) * SA_BYTES;
#pragma unroll
            for (int j = 0; j < 8; j++) {
                int row = wid * 32 + j * 4 + r4;
                int nbr = snbr[row * 9 + k2];
                cp_async16(base + row * 144 + li8 * 16,
                           (const char*)(src2 + (size_t)(nbr < 0 ? 0 : nbr) * 16) + li8 * 16,
                           nbr >= 0 ? 16 : 0);
            }
            CP_COMMIT();
            CP_WAIT1();
        } else {
            CP_WAIT0();
        }
        __syncwarp();

        uint32_t sAb_u = sA_u + (u & 1) * SA_BYTES;
        const uint2* wk = g_wtfH + u * 1024;
#pragma unroll
        for (int s = 0; s < 4; s++) {
            uint32_t a[2][4];
#pragma unroll
            for (int mi = 0; mi < 2; mi++) {
                uint32_t addr = sAb_u + (wid * 32 + mi * 16 + lrow) * 144 + s * 32 + lkh * 16;
                ldsm_x4(a[mi], addr);
            }
#pragma unroll
            for (int ni = 0; ni < 8; ni++) {
                uint2 bb = __ldg(wk + (s * 64 + ni * 8 + gid) * 4 + tig);
                mma_f16(acc[0][ni], a[0][0], a[0][1], a[0][2], a[0][3], bb.x, bb.y);
                mma_f16(acc[1][ni], a[1][0], a[1][1], a[1][2], a[1][3], bb.x, bb.y);
            }
        }
        __syncwarp();
    }

    // scattered epilogue: rank -> orig rows
#pragma unroll
    for (int mi = 0; mi < 2; mi++) {
        int row_s = p0 + wid * 32 + mi * 16 + gid;
        int ra = g_order[row_s];
        int rb = g_order[row_s + 8];
#pragma unroll
        for (int ni = 0; ni < 8; ni++) {
            int col = ni * 8 + tig * 2;
            float2 bb = *(const float2*)(bf + col);
            *(float2*)(out + (size_t)ra * 64 + col) =
                make_float2(acc[mi][ni][0] + bb.x, acc[mi][ni][1] + bb.y);
            *(float2*)(out + (size_t)rb * 64 + col) =
                make_float2(acc[mi][ni][2] + bb.x, acc[mi][ni][3] + bb.y);
        }
    }
}

// ---------------- launch ----------------
#define SMEM_CONV (2 * SA_BYTES + ROWS * 9 * 4)

extern "C" void kernel_launch(void* const* d_in, const int* in_sizes, int n_in,
                              void* d_out, int out_size)
{
    const float* feats = (const float*)d_in[0];
    const int*   idxs  = (const int*)  d_in[1];
    const int*   seg   = (const int*)  d_in[2];
    const float* w1    = (const float*)d_in[3];
    const float* b1    = (const float*)d_in[4];
    const float* w2    = (const float*)d_in[5];
    const float* b2    = (const float*)d_in[6];
    const float* w3    = (const float*)d_in[7];
    const float* b3    = (const float*)d_in[8];
    const float* wf    = (const float*)d_in[9];
    const float* bf    = (const float*)d_in[10];
    float* out = (float*)d_out;

    cudaFuncSetAttribute(k_branch_mma, cudaFuncAttributeMaxDynamicSharedMemorySize, SMEM_CONV);
    cudaFuncSetAttribute(k_final_mma,  cudaFuncAttributeMaxDynamicSharedMemorySize, SMEM_CONV);

    k_init<<<(Bn * Hn * Wn + 255) / 256, 256>>>();
    k_scatter<<<(Np + 255) / 256, 256>>>(idxs, seg);
    k_dil<<<1, 64>>>();
    k_count<<<1024, 1024>>>();
    k_scan<<<1, 1024>>>();
    k_emit<<<1024, 1024>>>(seg);
    k_prepw<<<(27648 + 36864 + 255) / 256, 256>>>(w1, w2, w3, wf);
    k_prepf<<<Np * 16 / 256, 256>>>(feats);

    dim3 gb(Np / ROWS, 3);
    k_branch_mma<<<gb, 256, SMEM_CONV>>>(idxs, b1, b2, b3);

    dim3 sg2(Np / 256, 3);
    k_stats2<<<sg2, 256>>>();
    k_normfin<<<12, 256>>>();
    k_hnorm<<<3 * Np * 16 / 256, 256>>>();

    k_final_mma<<<Np / ROWS, 256, SMEM_CONV>>>(idxs, bf, out);
}

// round 16
// speedup vs baseline: 1.0903x; 1.0903x over previous
#include <cuda_runtime.h>
#include <cuda_fp16.h>
#include <cstdint>

#define Np   262144
#define Bn   4
#define Hn   512
#define Wn   512
#define NINS 16
#define EPSF 1e-5f

// ---------------- device scratch ----------------
__device__ int      g_idx_map[Bn * Hn * Wn];
__device__ __align__(16) uint32_t g_hraw[3u * Np * 32u];   // raw h fp16
__device__ __align__(16) uint2    g_hn[3u * Np * 16u];     // relu(norm(h)) fp16
__device__ __align__(16) uint2    g_ftH[Np * 16u];         // feats fp16
__device__ float g_sum [3 * NINS * 64];
__device__ float g_sum2[3 * NINS * 64];
__device__ float g_mean[3 * NINS * 64];
__device__ float g_rinv[3 * NINS * 64];
__device__ int   g_cnt [NINS];
__device__ int   g_ymin[NINS], g_ymax[NINS], g_xmin[NINS], g_xmax[NINS];
__device__ int   g_dil[3 * NINS];
__device__ uint2 g_wtbH[3 * 9 * 1024];
__device__ uint2 g_wtfH[36 * 1024];

// ---------------- helpers ----------------
__device__ __forceinline__ void mma_f16(float* d, uint32_t a0, uint32_t a1,
                                        uint32_t a2, uint32_t a3,
                                        uint32_t b0, uint32_t b1) {
    asm volatile(
        "mma.sync.aligned.m16n8k16.row.col.f32.f16.f16.f32 "
        "{%0,%1,%2,%3}, {%4,%5,%6,%7}, {%8,%9}, {%0,%1,%2,%3};"
        : "+f"(d[0]), "+f"(d[1]), "+f"(d[2]), "+f"(d[3])
        : "r"(a0), "r"(a1), "r"(a2), "r"(a3), "r"(b0), "r"(b1));
}

__device__ __forceinline__ void ldsm_x4(uint32_t* r, uint32_t addr) {
    asm volatile("ldmatrix.sync.aligned.m8n8.x4.shared.b16 {%0,%1,%2,%3}, [%4];"
                 : "=r"(r[0]), "=r"(r[1]), "=r"(r[2]), "=r"(r[3]) : "r"(addr));
}

__device__ __forceinline__ uint32_t pack2(float x, float y) {
    __half2 h = __floats2half2_rn(x, y);
    return *(uint32_t*)&h;
}

// L2-direct 16B async copy (no L1 allocation; gathered rows have no reuse)
__device__ __forceinline__ void cp_async16(uint32_t dst, const void* src, int srcsize) {
    asm volatile("cp.async.cg.shared.global [%0], [%1], 16, %2;"
                 :: "r"(dst), "l"(src), "r"(srcsize) : "memory");
}
#define CP_COMMIT() asm volatile("cp.async.commit_group;" ::: "memory")
#define CP_WAIT1()  asm volatile("cp.async.wait_group 1;" ::: "memory")
#define CP_WAIT0()  asm volatile("cp.async.wait_group 0;" ::: "memory")

#define ROWS  256
#define SA_BYTES (ROWS * 144)

// ---------------- init / scatter / dil (proven) ----------------
__global__ void k_init() {
    int i = blockIdx.x * blockDim.x + threadIdx.x;
    if (i < Bn * Hn * Wn) g_idx_map[i] = -1;
    if (i < 3 * NINS * 64) { g_sum[i] = 0.f; g_sum2[i] = 0.f; }
    if (i < NINS) {
        g_cnt[i] = 0;
        g_ymin[i] = 0x7FFFFFFF; g_ymax[i] = 0x80000000;
        g_xmin[i] = 0x7FFFFFFF; g_xmax[i] = 0x80000000;
    }
}

__global__ void k_scatter(const int* __restrict__ idxs, const int* __restrict__ seg) {
    __shared__ int sy0[NINS], sy1[NINS], sx0[NINS], sx1[NINS], sc[NINS];
    int tid = threadIdx.x;
    if (tid < NINS) { sy0[tid] = 0x7FFFFFFF; sy1[tid] = 0x80000000;
                      sx0[tid] = 0x7FFFFFFF; sx1[tid] = 0x80000000; sc[tid] = 0; }
    __syncthreads();
    int i = blockIdx.x * blockDim.x + tid;
    if (i < Np) {
        int b = idxs[3*i], y = idxs[3*i+1], x = idxs[3*i+2];
        g_idx_map[(b * Hn + y) * Wn + x] = i;
        int s = seg[i];
        atomicMin(&sy0[s], y); atomicMax(&sy1[s], y);
        atomicMin(&sx0[s], x); atomicMax(&sx1[s], x);
        atomicAdd(&sc[s], 1);
    }
    __syncthreads();
    if (tid < NINS && sc[tid] > 0) {
        atomicMin(&g_ymin[tid], sy0[tid]); atomicMax(&g_ymax[tid], sy1[tid]);
        atomicMin(&g_xmin[tid], sx0[tid]); atomicMax(&g_xmax[tid], sx1[tid]);
        atomicAdd(&g_cnt[tid], sc[tid]);
    }
}

__global__ void k_dil() {
    int i = threadIdx.x;
    if (i < 3 * NINS) {
        int s = i & 15, r = i >> 4;
        int rate = (r == 0) ? 1 : (r == 1) ? 3 : 5;
        float hr = (float)(g_ymax[s] - g_ymin[s]) / (float)Hn;
        float wr = (float)(g_xmax[s] - g_xmin[s]) / (float)Wn;
        int d = (int)ceilf(fmaxf(hr, wr) * (float)rate);
        if (d < 1) d = 1;
        g_dil[r * NINS + s] = d;
    }
}

// ---------------- weight prep (proven) ----------------
__global__ void k_prepw(const float* __restrict__ w1, const float* __restrict__ w2,
                        const float* __restrict__ w3, const float* __restrict__ wf)
{
    int i = blockIdx.x * blockDim.x + threadIdx.x;
    if (i < 27648) {
        int br  = i / 9216;
        int r   = i % 9216;
        int tap = r / 1024;
        int r2  = r % 1024;
        int s   = r2 >> 8;
        int col = (r2 >> 2) & 63;
        int tig = r2 & 3;
        int kb  = s * 16 + tig * 2;
        const float* w = (br == 0) ? w1 : (br == 1) ? w2 : w3;
        const float* wt = w + tap * 4096;
        g_wtbH[i] = make_uint2(
            pack2(wt[(kb    ) * 64 + col], wt[(kb + 1) * 64 + col]),
            pack2(wt[(kb + 8) * 64 + col], wt[(kb + 9) * 64 + col]));
    } else if (i < 27648 + 36864) {
        int i2  = i - 27648;
        int u   = i2 / 1024;
        int r2  = i2 % 1024;
        int s   = r2 >> 8;
        int col = (r2 >> 2) & 63;
        int tig = r2 & 3;
        int tap = u >> 2, c = u & 3;
        int kb  = c * 64 + s * 16 + tig * 2;
        const float* wt = wf + (size_t)tap * 256 * 64;
        g_wtfH[i2] = make_uint2(
            pack2(wt[(kb    ) * 64 + col], wt[(kb + 1) * 64 + col]),
            pack2(wt[(kb + 8) * 64 + col], wt[(kb + 9) * 64 + col]));
    }
}

// ---------------- feats -> fp16 pre-convert ----------------
__global__ void __launch_bounds__(256) k_prepf(const float* __restrict__ feats) {
    int i = blockIdx.x * 256 + threadIdx.x;
    float4 f = ((const float4*)feats)[i];
    g_ftH[i] = make_uint2(pack2(f.x, f.y), pack2(f.z, f.w));
}

// ---------------- branch conv + fused stats: warp-autonomous mainloop ------
__global__ void __launch_bounds__(256, 2) k_branch_mma(
    const int* __restrict__ idxs, const int* __restrict__ seg,
    const float* __restrict__ bias1, const float* __restrict__ bias2,
    const float* __restrict__ bias3)
{
    extern __shared__ __half smh[];
    char* sA   = (char*)smh;                         // 2 x [256][144B]
    int*  snbr = (int*)(sA + 2 * SA_BYTES);          // 256*9

    int tid = threadIdx.x;
    int br  = blockIdx.y;
    int p0  = blockIdx.x * ROWS;
    const float* bias = (br == 0) ? bias1 : (br == 1) ? bias2 : bias3;

    for (int t = tid; t < ROWS * 9; t += 256) {
        int p = t / 9, k = t % 9;
        int gi = p0 + p;
        int b = idxs[3*gi], y = idxs[3*gi+1], x = idxs[3*gi+2];
        int sgi = seg[gi];
        int d = g_dil[br * NINS + sgi];
        int ky = k / 3 - 1, kx = k % 3 - 1;
        int ny = y + ky * d, nx = x + kx * d;
        int nbr = -1;
        if (ny >= 0 && ny < Hn && nx >= 0 && nx < Wn) {
            int n = g_idx_map[(b * Hn + ny) * Wn + nx];
            if (n >= 0 && seg[n] == sgi) nbr = n;
        }
        snbr[t] = nbr;
    }
    __syncthreads();

    int lane = tid & 31, wid = tid >> 5;
    int gid = lane >> 2, tig = lane & 3;
    int li8 = lane & 7, r4 = lane >> 3;       // fill: 8 lanes x 16B per row, 4 rows/instr
    int lrow = lane & 15, lkh = lane >> 4;    // ldmatrix

    uint32_t sA_u = (uint32_t)__cvta_generic_to_shared(sA);

    float acc[2][8][4];
#pragma unroll
    for (int mi = 0; mi < 2; mi++)
#pragma unroll
        for (int ni = 0; ni < 8; ni++)
#pragma unroll
            for (int e = 0; e < 4; e++) acc[mi][ni][e] = 0.f;

    const uint2* wtb = g_wtbH + (size_t)(br * 9) * 1024;

    // prefetch tap 0: warp fills its OWN 32 rows
    {
#pragma unroll
        for (int j = 0; j < 8; j++) {
            int row = wid * 32 + j * 4 + r4;
            int nbr = snbr[row * 9];
            cp_async16(sA_u + row * 144 + li8 * 16,
                       (const char*)(g_ftH + (size_t)(nbr < 0 ? 0 : nbr) * 16) + li8 * 16,
                       nbr >= 0 ? 16 : 0);
        }
        CP_COMMIT();
    }

    for (int k = 0; k < 9; k++) {
        if (k < 8) {
            uint32_t base = sA_u + ((k + 1) & 1) * SA_BYTES;
#pragma unroll
            for (int j = 0; j < 8; j++) {
                int row = wid * 32 + j * 4 + r4;
                int nbr = snbr[row * 9 + k + 1];
                cp_async16(base + row * 144 + li8 * 16,
                           (const char*)(g_ftH + (size_t)(nbr < 0 ? 0 : nbr) * 16) + li8 * 16,
                           nbr >= 0 ? 16 : 0);
            }
            CP_COMMIT();
            CP_WAIT1();
        } else {
            CP_WAIT0();
        }
        __syncwarp();

        uint32_t sAb_u = sA_u + (k & 1) * SA_BYTES;
        const uint2* wk = wtb + k * 1024;
#pragma unroll
        for (int s = 0; s < 4; s++) {
            uint32_t a[2][4];
#pragma unroll
            for (int mi = 0; mi < 2; mi++) {
                uint32_t addr = sAb_u + (wid * 32 + mi * 16 + lrow) * 144 + s * 32 + lkh * 16;
                ldsm_x4(a[mi], addr);
            }
#pragma unroll
            for (int ni = 0; ni < 8; ni++) {
                uint2 bb = __ldg(wk + (s * 64 + ni * 8 + gid) * 4 + tig);
                mma_f16(acc[0][ni], a[0][0], a[0][1], a[0][2], a[0][3], bb.x, bb.y);
                mma_f16(acc[1][ni], a[1][0], a[1][1], a[1][2], a[1][3], bb.x, bb.y);
            }
        }
        __syncwarp();
    }

    // add bias, write raw h fp16
    uint32_t* hout = g_hraw + (size_t)br * Np * 32;
#pragma unroll
    for (int ni = 0; ni < 8; ni++) {
        int col = ni * 8 + tig * 2;
        float2 bb = *(const float2*)(bias + col);
#pragma unroll
        for (int mi = 0; mi < 2; mi++) {
            acc[mi][ni][0] += bb.x; acc[mi][ni][1] += bb.y;
            acc[mi][ni][2] += bb.x; acc[mi][ni][3] += bb.y;
            int row = p0 + wid * 32 + mi * 16 + gid;
            hout[(size_t)row * 32 + (col >> 1)] = pack2(acc[mi][ni][0], acc[mi][ni][1]);
            hout[(size_t)(row + 8) * 32 + (col >> 1)] = pack2(acc[mi][ni][2], acc[mi][ni][3]);
        }
    }

    // fused segment stats (per-warp 32-row span)
    int sg0 = seg[p0 + wid * 32], sg1 = seg[p0 + wid * 32 + 31];
    if (sg0 == sg1) {
#pragma unroll
        for (int ni = 0; ni < 8; ni++) {
            float s0 = acc[0][ni][0] + acc[0][ni][2] + acc[1][ni][0] + acc[1][ni][2];
            float s1 = acc[0][ni][1] + acc[0][ni][3] + acc[1][ni][1] + acc[1][ni][3];
            float q0 = acc[0][ni][0]*acc[0][ni][0] + acc[0][ni][2]*acc[0][ni][2]
                     + acc[1][ni][0]*acc[1][ni][0] + acc[1][ni][2]*acc[1][ni][2];
            float q1 = acc[0][ni][1]*acc[0][ni][1] + acc[0][ni][3]*acc[0][ni][3]
                     + acc[1][ni][1]*acc[1][ni][1] + acc[1][ni][3]*acc[1][ni][3];
#pragma unroll
            for (int m = 4; m < 32; m <<= 1) {
                s0 += __shfl_xor_sync(0xFFFFFFFF, s0, m);
                s1 += __shfl_xor_sync(0xFFFFFFFF, s1, m);
                q0 += __shfl_xor_sync(0xFFFFFFFF, q0, m);
                q1 += __shfl_xor_sync(0xFFFFFFFF, q1, m);
            }
            if (gid == 0) {
                int col = ni * 8 + tig * 2;
                int tb = (br * NINS + sg0) * 64 + col;
                atomicAdd(&g_sum [tb],     s0);
                atomicAdd(&g_sum [tb + 1], s1);
                atomicAdd(&g_sum2[tb],     q0);
                atomicAdd(&g_sum2[tb + 1], q1);
            }
        }
    } else {
#pragma unroll
        for (int ni = 0; ni < 8; ni++) {
            int col = ni * 8 + tig * 2;
#pragma unroll
            for (int mi = 0; mi < 2; mi++) {
                int rowa = p0 + wid * 32 + mi * 16 + gid;
                int rowb = rowa + 8;
                int sa = seg[rowa], sb = seg[rowb];
                int ta  = (br * NINS + sa) * 64 + col;
                int tb2 = (br * NINS + sb) * 64 + col;
                atomicAdd(&g_sum [ta],      acc[mi][ni][0]);
                atomicAdd(&g_sum [ta + 1],  acc[mi][ni][1]);
                atomicAdd(&g_sum2[ta],      acc[mi][ni][0]*acc[mi][ni][0]);
                atomicAdd(&g_sum2[ta + 1],  acc[mi][ni][1]*acc[mi][ni][1]);
                atomicAdd(&g_sum [tb2],     acc[mi][ni][2]);
                atomicAdd(&g_sum [tb2 + 1], acc[mi][ni][3]);
                atomicAdd(&g_sum2[tb2],     acc[mi][ni][2]*acc[mi][ni][2]);
                atomicAdd(&g_sum2[tb2 + 1], acc[mi][ni][3]*acc[mi][ni][3]);
            }
        }
    }
}

__global__ void k_normfin() {
    int i = blockIdx.x * blockDim.x + threadIdx.x;
    if (i < 3 * NINS * 64) {
        int sgl = (i / 64) % NINS;
        float cnt = (float)g_cnt[sgl];
        float mean = g_sum[i] / cnt;
        float var  = g_sum2[i] / cnt - mean * mean;
        g_mean[i] = mean;
        g_rinv[i] = rsqrtf(var + EPSF);
    }
}

// ---------------- normalize + relu (fp16 in/out) ----------------
__global__ void __launch_bounds__(256) k_hnorm(const int* __restrict__ seg) {
    int i = blockIdx.x * 256 + threadIdx.x;
    int br  = i / (Np * 16);
    int rem = i % (Np * 16);
    int p   = rem >> 4;
    int c4  = rem & 15;
    int sg  = seg[p];
    uint2 raw = ((const uint2*)g_hraw)[i];
    float2 f01 = __half22float2(*reinterpret_cast<const __half2*>(&raw.x));
    float2 f23 = __half22float2(*reinterpret_cast<const __half2*>(&raw.y));
    int tb = ((br * NINS + sg) << 6) + c4 * 4;
    float4 mm = *(const float4*)(g_mean + tb);
    float4 rr = *(const float4*)(g_rinv + tb);
    float x0 = fmaxf(0.f, (f01.x - mm.x) * rr.x);
    float x1 = fmaxf(0.f, (f01.y - mm.y) * rr.y);
    float x2 = fmaxf(0.f, (f23.x - mm.z) * rr.z);
    float x3 = fmaxf(0.f, (f23.y - mm.w) * rr.w);
    g_hn[i] = make_uint2(pack2(x0, x1), pack2(x2, x3));
}

// ---------------- final conv: warp-autonomous mainloop ----------------------
__global__ void __launch_bounds__(256, 2) k_final_mma(
    const int* __restrict__ idxs, const float* __restrict__ bf,
    float* __restrict__ out)
{
    extern __shared__ __half smh[];
    char* sA   = (char*)smh;
    int*  snbr = (int*)(sA + 2 * SA_BYTES);

    int tid = threadIdx.x;
    int p0  = blockIdx.x * ROWS;

    for (int t = tid; t < ROWS * 9; t += 256) {
        int p = t / 9, k = t % 9;
        int gi = p0 + p;
        int b = idxs[3*gi], y = idxs[3*gi+1], x = idxs[3*gi+2];
        int ky = k / 3 - 1, kx = k % 3 - 1;
        int ny = y + ky, nx = x + kx;
        int nbr = -1;
        if (ny >= 0 && ny < Hn && nx >= 0 && nx < Wn)
            nbr = g_idx_map[(b * Hn + ny) * Wn + nx];
        snbr[t] = nbr;
    }
    __syncthreads();

    int lane = tid & 31, wid = tid >> 5;
    int gid = lane >> 2, tig = lane & 3;
    int li8 = lane & 7, r4 = lane >> 3;
    int lrow = lane & 15, lkh = lane >> 4;

    uint32_t sA_u = (uint32_t)__cvta_generic_to_shared(sA);

    float acc[2][8][4];
#pragma unroll
    for (int mi = 0; mi < 2; mi++)
#pragma unroll
        for (int ni = 0; ni < 8; ni++)
#pragma unroll
            for (int e = 0; e < 4; e++) acc[mi][ni][e] = 0.f;

    {
#pragma unroll
        for (int j = 0; j < 8; j++) {
            int row = wid * 32 + j * 4 + r4;
            int nbr = snbr[row * 9];
            cp_async16(sA_u + row * 144 + li8 * 16,
                       (const char*)(g_ftH + (size_t)(nbr < 0 ? 0 : nbr) * 16) + li8 * 16,
                       nbr >= 0 ? 16 : 0);
        }
        CP_COMMIT();
    }

    for (int u = 0; u < 36; u++) {
        if (u < 35) {
            int k2 = (u + 1) >> 2, c2 = (u + 1) & 3;
            const uint2* src2 = (c2 == 0) ? g_ftH : (g_hn + (size_t)(c2 - 1) * Np * 16);
            uint32_t base = sA_u + ((u + 1) & 1) * SA_BYTES;
#pragma unroll
            for (int j = 0; j < 8; j++) {
                int row = wid * 32 + j * 4 + r4;
                int nbr = snbr[row * 9 + k2];
                cp_async16(base + row * 144 + li8 * 16,
                           (const char*)(src2 + (size_t)(nbr < 0 ? 0 : nbr) * 16) + li8 * 16,
                           nbr >= 0 ? 16 : 0);
            }
            CP_COMMIT();
            CP_WAIT1();
        } else {
            CP_WAIT0();
        }
        __syncwarp();

        uint32_t sAb_u = sA_u + (u & 1) * SA_BYTES;
        const uint2* wk = g_wtfH + u * 1024;
#pragma unroll
        for (int s = 0; s < 4; s++) {
            uint32_t a[2][4];
#pragma unroll
            for (int mi = 0; mi < 2; mi++) {
                uint32_t addr = sAb_u + (wid * 32 + mi * 16 + lrow) * 144 + s * 32 + lkh * 16;
                ldsm_x4(a[mi], addr);
            }
#pragma unroll
            for (int ni = 0; ni < 8; ni++) {
                uint2 bb = __ldg(wk + (s * 64 + ni * 8 + gid) * 4 + tig);
                mma_f16(acc[0][ni], a[0][0], a[0][1], a[0][2], a[0][3], bb.x, bb.y);
                mma_f16(acc[1][ni], a[1][0], a[1][1], a[1][2], a[1][3], bb.x, bb.y);
            }
        }
        __syncwarp();
    }

#pragma unroll
    for (int ni = 0; ni < 8; ni++) {
        int col = ni * 8 + tig * 2;
        float2 bb = *(const float2*)(bf + col);
#pragma unroll
        for (int mi = 0; mi < 2; mi++) {
            int row = p0 + wid * 32 + mi * 16 + gid;
            float2 v0 = make_float2(acc[mi][ni][0] + bb.x, acc[mi][ni][1] + bb.y);
            float2 v1 = make_float2(acc[mi][ni][2] + bb.x, acc[mi][ni][3] + bb.y);
            *(float2*)(out + (size_t)row * 64 + col) = v0;
            *(float2*)(out + (size_t)(row + 8) * 64 + col) = v1;
        }
    }
}

// ---------------- launch ----------------
#define SMEM_CONV (2 * SA_BYTES + ROWS * 9 * 4)

extern "C" void kernel_launch(void* const* d_in, const int* in_sizes, int n_in,
                              void* d_out, int out_size)
{
    const float* feats = (const float*)d_in[0];
    const int*   idxs  = (const int*)  d_in[1];
    const int*   seg   = (const int*)  d_in[2];
    const float* w1    = (const float*)d_in[3];
    const float* b1    = (const float*)d_in[4];
    const float* w2    = (const float*)d_in[5];
    const float* b2    = (const float*)d_in[6];
    const float* w3    = (const float*)d_in[7];
    const float* b3    = (const float*)d_in[8];
    const float* wf    = (const float*)d_in[9];
    const float* bf    = (const float*)d_in[10];
    float* out = (float*)d_out;

    cudaFuncSetAttribute(k_branch_mma, cudaFuncAttributeMaxDynamicSharedMemorySize, SMEM_CONV);
    cudaFuncSetAttribute(k_final_mma,  cudaFuncAttributeMaxDynamicSharedMemorySize, SMEM_CONV);

    k_init<<<(Bn * Hn * Wn + 255) / 256, 256>>>();
    k_scatter<<<(Np + 255) / 256, 256>>>(idxs, seg);
    k_dil<<<1, 64>>>();
    k_prepw<<<(27648 + 36864 + 255) / 256, 256>>>(w1, w2, w3, wf);
    k_prepf<<<Np * 16 / 256, 256>>>(feats);

    dim3 gb(Np / ROWS, 3);
    k_branch_mma<<<gb, 256, SMEM_CONV>>>(idxs, seg, b1, b2, b3);

    k_normfin<<<12, 256>>>();
    k_hnorm<<<3 * Np * 16 / 256, 256>>>(seg);

    k_final_mma<<<Np / ROWS, 256, SMEM_CONV>>>(idxs, bf, out);
}